// round 15
// baseline (speedup 1.0000x reference)
#include <cuda_runtime.h>
#include <math.h>

// ---------------------------------------------------------------------------
// NeuralODE on GB300 (round 14): r10 structure (best: 1178us) + antithetic
// wave-1 placement. Classic (cluster=1) placement maps bids b and b+148 to
// the same SM, so wave 1 pairs each of the 148 LONGEST pairs with one of the
// 148 SHORTEST (which finish almost immediately) -> the critical CTA runs
// mostly solo, shortening the 1016-eval chain. Remaining mids launch
// longest-first (LPT refill).
//  * 512 CTAs x 256 threads, RR=2, 2 CTAs/SM
//  * broadcast layer-2 (warp-uniform h1 reads), W2/W1/W3/b2 in registers
//  * rows counting-sorted by length; pair skip = max(pair tend)
//  * fma.rn.f32x2 / add.rn.f32x2, MUFU tanh.approx
// ---------------------------------------------------------------------------

#define Bsz   1024
#define Tn    128
#define Dn    256
#define NACT  9
#define LATD  32
#define INW   43
#define RR    2
#define NCTA  512
#define NTH   256

typedef unsigned long long u64;

__device__ int g_perm[Bsz];

__device__ __forceinline__ u64 fma2(u64 a, u64 b, u64 c) {
    u64 d;
    asm("fma.rn.f32x2 %0, %1, %2, %3;" : "=l"(d) : "l"(a), "l"(b), "l"(c));
    return d;
}
__device__ __forceinline__ u64 add2(u64 a, u64 b) {
    u64 d;
    asm("add.rn.f32x2 %0, %1, %2;" : "=l"(d) : "l"(a), "l"(b));
    return d;
}
__device__ __forceinline__ float2 unpk(u64 v) {
    float2 f;
    asm("mov.b64 {%0, %1}, %2;" : "=f"(f.x), "=f"(f.y) : "l"(v));
    return f;
}
__device__ __forceinline__ float tanh_fast(float x) {
    float r;
    asm("tanh.approx.f32 %0, %1;" : "=f"(r) : "f"(x));
    return r;
}

// ---- counting sort of rows by length (stable, deterministic) --------------
__global__ void sort_kernel(const int* __restrict__ length)
{
    __shared__ int len_s[Bsz];
    __shared__ int hist[Tn];
    __shared__ int pref[Tn];
    const int tid = threadIdx.x;          // 128 threads
    for (int i = tid; i < Bsz; i += 128) {
        int v = length[i];
        len_s[i] = min(max(v, 0), Tn - 1);
    }
    if (tid < Tn) hist[tid] = 0;
    __syncthreads();
    for (int i = tid; i < Bsz; i += 128) atomicAdd(&hist[len_s[i]], 1);
    __syncthreads();
    if (tid == 0) {
        int acc = 0;
        for (int v = 0; v < Tn; v++) { pref[v] = acc; acc += hist[v]; }
    }
    __syncthreads();
    int pos = pref[tid];                  // thread tid handles bin value tid
    for (int b = 0; b < Bsz; b++)
        if (len_s[b] == tid) g_perm[pos++] = b;
}

struct __align__(16) Smem {
    float h1[RR][128];
    float h2[RR][128];
    float part[2][RR][128];   // [k-half][row][unit]
    float csr[RR][Dn];
    float Yts[RR][12];
    float Ycur[RR][12];
    float ksum[RR][12];
    float b3s[16];
    float tsm[Tn];
    float tend[RR];
    float tendmax;
    int   brow[RR];
};

__global__ __launch_bounds__(NTH, 2)
void node_kernel(const float* __restrict__ ts, const float* __restrict__ y0,
                 const float* __restrict__ latent, const int* __restrict__ length,
                 const float* __restrict__ dense_ts, const float* __restrict__ dense_cs,
                 const float* __restrict__ W1, const float* __restrict__ b1,
                 const float* __restrict__ W2, const float* __restrict__ b2,
                 const float* __restrict__ W3, const float* __restrict__ b3,
                 float* __restrict__ out)
{
    __shared__ Smem s;
    const int tid = threadIdx.x;
    // Antithetic wave-1 placement (bids b and b+148 share an SM):
    //   b in [0,148)   -> longest pairs (grp 511..364)
    //   b in [148,296) -> shortest pairs (grp 0..147), die fast -> long runs solo
    //   b in [296,512) -> middles, longest-first (LPT refill: grp 363..148)
    const int b_  = blockIdx.x;
    const int grp = (b_ < 148) ? (511 - b_)
                  : (b_ < 296) ? (b_ - 148)
                               : (659 - b_);

    if (tid < RR) {
        int b = g_perm[grp * RR + tid];
        s.brow[tid] = b;
        s.tend[tid] = ts[max(length[b] - 1, 0)];
    }
    if (tid < Tn) s.tsm[tid] = ts[tid];
    if (tid < NACT) s.b3s[tid] = b3[tid];
    if (tid < RR * 12) {
        int r = tid / 12, d = tid % 12;
        s.Yts[r][d] = 0.f; s.Ycur[r][d] = 0.f; s.ksum[r][d] = 0.f;
    }
    __syncthreads();
    if (tid == 0) s.tendmax = fmaxf(s.tend[0], s.tend[1]);

    // ---- per-thread register state ---------------------------------------
    // layer-1 & combine: thread = (unit u1, row e)
    const int u1 = tid & 127;
    const int e  = tid >> 7;
    // layer-2: warp-uniform k-half -> broadcast h1 reads
    const int w  = tid >> 5;
    const int l  = tid & 31;
    const int h  = w >> 2;               // warps 0-3: k in [0,64); warps 4-7: [64,128)
    const int u2 = (w & 3) * 32 + l;     // unit 0..127

    u64 W2r[32];
    {
        const u64* wg = reinterpret_cast<const u64*>(W2 + u2 * 128 + h * 64);
        #pragma unroll
        for (int m = 0; m < 32; m++) W2r[m] = wg[m];
    }
    const float b2r = b2[u1];

    // layer-1: W1 coefficients + folded latent bias for (u1, e)
    float w1a[NACT], w1t, w1c, base1;
    {
        const float* W1r = W1 + u1 * INW;
        #pragma unroll
        for (int i = 0; i < NACT; i++) w1a[i] = W1r[i];
        w1t = W1r[41];
        w1c = W1r[42];
        const float* lv = latent + g_perm[grp * RR + e] * LATD;
        float acc = b1[u1];
        #pragma unroll
        for (int li = 0; li < LATD; li++) acc = fmaf(W1r[9 + li], lv[li], acc);
        base1 = acc;
    }

    // layer-3 (threads 0..143): W3 slice in regs; (q = tid&7, r = (tid>>3)&1, i3 = tid>>4)
    float4 w3r[4];
    if (tid < 144) {
        const float* wg = W3 + (tid >> 4) * 128 + (tid & 7) * 16;
        #pragma unroll
        for (int kk = 0; kk < 4; kk++)
            w3r[kk] = *reinterpret_cast<const float4*>(wg + kk * 4);
    }

    for (int idx = tid; idx < RR * Dn; idx += NTH) {
        int r = idx >> 8, d = idx & 255;
        s.csr[r][d] = dense_cs[s.brow[r] * Dn + d];
    }
    __syncthreads();
    if (tid < RR) {
        float y = y0[s.brow[tid]];
        s.Yts[tid][0] = y; s.Ycur[tid][0] = y;
        out[s.brow[tid] * Tn] = y;       // t = 0 sample
    }
    __syncthreads();

    // ---- time integration -------------------------------------------------
    for (int step = 0; step < Tn - 1; step++) {
        const float ta  = s.tsm[step];
        const float dtf = (s.tsm[step + 1] - ta) * 0.5f;
        if (ta <= s.tendmax) {
            for (int sub = 0; sub < 2; sub++) {
                const float t0 = ta + sub * dtf;
                for (int st = 0; st < 4; st++) {
                    const float t = t0 + ((st == 0) ? 0.f : (st == 3) ? dtf : 0.5f * dtf);

                    // ---- layer 1: all 256 threads, one (unit,row) each ----
                    {
                        int ii = (int)ceilf(t);
                        ii = max(1, min(Dn - 1, ii));
                        float wc = t - (float)(ii - 1);
                        wc = fminf(fmaxf(wc, 0.f), 1.f);
                        float cl = s.csr[e][ii - 1];
                        float c  = fmaf(wc, s.csr[e][ii] - cl, cl);
                        float4 yA = *reinterpret_cast<const float4*>(&s.Yts[e][0]);
                        float4 yB = *reinterpret_cast<const float4*>(&s.Yts[e][4]);
                        float  y8 = s.Yts[e][8];
                        float a0 = base1;
                        float a1 = w1t * t;
                        a0 = fmaf(w1c,   c,    a0);
                        a1 = fmaf(w1a[0], yA.x, a1);
                        a0 = fmaf(w1a[1], yA.y, a0);
                        a1 = fmaf(w1a[2], yA.z, a1);
                        a0 = fmaf(w1a[3], yA.w, a0);
                        a1 = fmaf(w1a[4], yB.x, a1);
                        a0 = fmaf(w1a[5], yB.y, a0);
                        a1 = fmaf(w1a[6], yB.z, a1);
                        a0 = fmaf(w1a[7], yB.w, a0);
                        a1 = fmaf(w1a[8], y8,   a1);
                        s.h1[e][u1] = tanh_fast(a0 + a1);
                    }
                    __syncthreads();

                    // ---- layer 2 partials: broadcast h1, register W2, 2 rows
                    {
                        #pragma unroll
                        for (int r = 0; r < RR; r++) {
                            u64 a0 = 0ull, a1 = 0ull, a2 = 0ull, a3 = 0ull;
                            const ulonglong2* hb =
                                reinterpret_cast<const ulonglong2*>(&s.h1[r][h * 64]);
                            #pragma unroll
                            for (int m = 0; m < 8; m++) {
                                ulonglong2 v0 = hb[2 * m];   // warp-uniform addr: broadcast
                                a0 = fma2(W2r[4 * m],     v0.x, a0);
                                a1 = fma2(W2r[4 * m + 1], v0.y, a1);
                                ulonglong2 v1 = hb[2 * m + 1];
                                a2 = fma2(W2r[4 * m + 2], v1.x, a2);
                                a3 = fma2(W2r[4 * m + 3], v1.y, a3);
                            }
                            float2 f = unpk(add2(add2(a0, a1), add2(a2, a3)));
                            s.part[h][r][u2] = f.x + f.y;
                        }
                    }
                    __syncthreads();

                    // ---- layer 2 combine: all 256 threads (unit,row) ----
                    s.h2[e][u1] = tanh_fast(s.part[0][e][u1] + s.part[1][e][u1] + b2r);
                    __syncthreads();

                    // ---- layer 3 + constraint + gating + RK bookkeeping ----
                    // 144 threads = warps 0-3 full + lanes 0..15 of warp 4
                    if (tid < 144) {
                        const unsigned mask = (tid < 128) ? 0xffffffffu : 0x0000ffffu;
                        const int q  = tid & 7;          // 16-k slice
                        const int r  = (tid >> 3) & 1;   // row
                        const int i3 = tid >> 4;         // output unit 0..8
                        const float4* hv = reinterpret_cast<const float4*>(&s.h2[r][q * 16]);
                        float ax = 0.f, ay = 0.f, az = 0.f, aw = 0.f;
                        #pragma unroll
                        for (int kk = 0; kk < 4; kk++) {
                            float4 a = w3r[kk], b = hv[kk];
                            ax = fmaf(a.x, b.x, ax);
                            ay = fmaf(a.y, b.y, ay);
                            az = fmaf(a.z, b.z, az);
                            aw = fmaf(a.w, b.w, aw);
                        }
                        float acc = (ax + ay) + (az + aw);
                        acc += __shfl_xor_sync(mask, acc, 1);
                        acc += __shfl_xor_sync(mask, acc, 2);
                        acc += __shfl_xor_sync(mask, acc, 4);
                        if (q == 0) {
                            acc += s.b3s[i3];
                            if (i3 == 0) acc = -__cosf(acc);
                            if (t > s.tend[r]) acc = 0.f;     // per-sample stop
                            float ks;
                            if (st == 0) { ks = acc; s.ksum[r][i3] = ks; }
                            else {
                                ks = s.ksum[r][i3];
                                if (st < 3) { ks += 2.f * acc; s.ksum[r][i3] = ks; }
                            }
                            if (st < 3) {
                                float cY = (st == 2) ? dtf : 0.5f * dtf;
                                s.Yts[r][i3] = s.Ycur[r][i3] + cY * acc;
                            } else {
                                float y = s.Ycur[r][i3]
                                        + (dtf * (1.0f / 6.0f)) * (ks + acc);
                                s.Ycur[r][i3] = y;
                                s.Yts[r][i3]  = y;
                            }
                        }
                    }
                    __syncthreads();
                }
            }
        }
        if (tid < RR)
            out[s.brow[tid] * Tn + step + 1] = s.Ycur[tid][0];
    }
}

extern "C" void kernel_launch(void* const* d_in, const int* in_sizes, int n_in,
                              void* d_out, int out_size)
{
    (void)in_sizes; (void)n_in; (void)out_size;
    sort_kernel<<<1, 128>>>((const int*)d_in[3]);
    node_kernel<<<NCTA, NTH>>>(
        (const float*)d_in[0],   // ts
        (const float*)d_in[1],   // y0
        (const float*)d_in[2],   // latent_vec
        (const int*)  d_in[3],   // length
        (const float*)d_in[4],   // dense_ts (arange -> index math)
        (const float*)d_in[5],   // dense_cs
        (const float*)d_in[6],   // W1
        (const float*)d_in[7],   // b1
        (const float*)d_in[8],   // W2
        (const float*)d_in[9],   // b2
        (const float*)d_in[10],  // W3
        (const float*)d_in[11],  // b3
        (float*)d_out);
}

// round 16
// speedup vs baseline: 1.7132x; 1.7132x over previous
#include <cuda_runtime.h>
#include <math.h>

// ---------------------------------------------------------------------------
// NeuralODE on GB300 (round 16): r10 (best, 1178us, plain LPT) + two additive
// chain-cutting changes:
//  1) EXACT per-row dead-skip: when ta > tend[r], row r's vf == 0 and Y is
//     frozen -> skip its layer-1/layer-2/combine (CTA-uniform branches).
//     Layer-3 untouched (static shfl masks; computes acc then zeroes it).
//  2) Top-64 longest rows -> singleton CTAs (row duplicated into slot 1 with
//     tend = -1, permanently dead -> skipped) => critical chain per-eval cost
//     ~0.7x. Remaining 960 rows -> 480 pair CTAs. Grid 544, longest-first.
//  * 256 threads, RR=2, 2 CTAs/SM; broadcast layer-2; W2/W1/W3 in registers
//  * rows counting-sorted by length; fma.rn.f32x2; MUFU tanh.approx
// ---------------------------------------------------------------------------

#define Bsz   1024
#define Tn    128
#define Dn    256
#define NACT  9
#define LATD  32
#define INW   43
#define RR    2
#define NSINGLE 64
#define NCTA  (NSINGLE + (Bsz - NSINGLE) / 2)   // 64 + 480 = 544
#define NTH   256

typedef unsigned long long u64;

__device__ int g_perm[Bsz];

__device__ __forceinline__ u64 fma2(u64 a, u64 b, u64 c) {
    u64 d;
    asm("fma.rn.f32x2 %0, %1, %2, %3;" : "=l"(d) : "l"(a), "l"(b), "l"(c));
    return d;
}
__device__ __forceinline__ u64 add2(u64 a, u64 b) {
    u64 d;
    asm("add.rn.f32x2 %0, %1, %2;" : "=l"(d) : "l"(a), "l"(b));
    return d;
}
__device__ __forceinline__ float2 unpk(u64 v) {
    float2 f;
    asm("mov.b64 {%0, %1}, %2;" : "=f"(f.x), "=f"(f.y) : "l"(v));
    return f;
}
__device__ __forceinline__ float tanh_fast(float x) {
    float r;
    asm("tanh.approx.f32 %0, %1;" : "=f"(r) : "f"(x));
    return r;
}

// ---- counting sort of rows by length (stable, deterministic) --------------
__global__ void sort_kernel(const int* __restrict__ length)
{
    __shared__ int len_s[Bsz];
    __shared__ int hist[Tn];
    __shared__ int pref[Tn];
    const int tid = threadIdx.x;          // 128 threads
    for (int i = tid; i < Bsz; i += 128) {
        int v = length[i];
        len_s[i] = min(max(v, 0), Tn - 1);
    }
    if (tid < Tn) hist[tid] = 0;
    __syncthreads();
    for (int i = tid; i < Bsz; i += 128) atomicAdd(&hist[len_s[i]], 1);
    __syncthreads();
    if (tid == 0) {
        int acc = 0;
        for (int v = 0; v < Tn; v++) { pref[v] = acc; acc += hist[v]; }
    }
    __syncthreads();
    int pos = pref[tid];                  // thread tid handles bin value tid
    for (int b = 0; b < Bsz; b++)
        if (len_s[b] == tid) g_perm[pos++] = b;
}

struct __align__(16) Smem {
    float h1[RR][128];
    float h2[RR][128];
    float part[2][RR][128];   // [k-half][row][unit]
    float csr[RR][Dn];
    float Yts[RR][12];
    float Ycur[RR][12];
    float ksum[RR][12];
    float b3s[16];
    float tsm[Tn];
    float tend[RR];
    float tendmax;
    int   brow[RR];
};

__global__ __launch_bounds__(NTH, 2)
void node_kernel(const float* __restrict__ ts, const float* __restrict__ y0,
                 const float* __restrict__ latent, const int* __restrict__ length,
                 const float* __restrict__ dense_ts, const float* __restrict__ dense_cs,
                 const float* __restrict__ W1, const float* __restrict__ b1,
                 const float* __restrict__ W2, const float* __restrict__ b2,
                 const float* __restrict__ W3, const float* __restrict__ b3,
                 float* __restrict__ out)
{
    __shared__ Smem s;
    const int tid = threadIdx.x;
    const int b_  = blockIdx.x;

    // Assignment (longest-first = LPT):
    //   bid 0..63    -> singleton: rank 1023-bid (the 64 longest rows);
    //                   slot 1 = duplicate row, tend = -1 (always dead)
    //   bid 64..543  -> pair p = bid-64: ranks (959-2p, 958-2p)
    if (tid < RR) {
        int rankA, rk;
        bool dead;
        if (b_ < NSINGLE) { rankA = 1023 - b_; rk = rankA; dead = (tid == 1); }
        else {
            int p = b_ - NSINGLE;
            rankA = 959 - 2 * p;
            rk = rankA - tid;            // tid 0 -> hi rank, tid 1 -> lo rank
            dead = false;
        }
        int b = g_perm[rk];
        s.brow[tid] = b;
        s.tend[tid] = dead ? -1.0f : ts[max(length[b] - 1, 0)];
    }
    if (tid < Tn) s.tsm[tid] = ts[tid];
    if (tid < NACT) s.b3s[tid] = b3[tid];
    if (tid < RR * 12) {
        int r = tid / 12, d = tid % 12;
        s.Yts[r][d] = 0.f; s.Ycur[r][d] = 0.f; s.ksum[r][d] = 0.f;
    }
    __syncthreads();
    if (tid == 0) s.tendmax = fmaxf(s.tend[0], s.tend[1]);

    // ---- per-thread register state ---------------------------------------
    // layer-1 & combine: thread = (unit u1, row e)
    const int u1 = tid & 127;
    const int e  = tid >> 7;
    // layer-2: warp-uniform k-half -> broadcast h1 reads
    const int w  = tid >> 5;
    const int l  = tid & 31;
    const int h  = w >> 2;               // warps 0-3: k in [0,64); warps 4-7: [64,128)
    const int u2 = (w & 3) * 32 + l;     // unit 0..127

    u64 W2r[32];
    {
        const u64* wg = reinterpret_cast<const u64*>(W2 + u2 * 128 + h * 64);
        #pragma unroll
        for (int m = 0; m < 32; m++) W2r[m] = wg[m];
    }
    const float b2r = b2[u1];

    // layer-1: W1 coefficients + folded latent bias for (u1, e)
    float w1a[NACT], w1t, w1c, base1;
    {
        const float* W1r = W1 + u1 * INW;
        #pragma unroll
        for (int i = 0; i < NACT; i++) w1a[i] = W1r[i];
        w1t = W1r[41];
        w1c = W1r[42];
        const float* lv = latent + s.brow[e] * LATD;
        float acc = b1[u1];
        #pragma unroll
        for (int li = 0; li < LATD; li++) acc = fmaf(W1r[9 + li], lv[li], acc);
        base1 = acc;
    }

    // layer-3 (threads 0..143): W3 slice in regs; (q = tid&7, r = (tid>>3)&1, i3 = tid>>4)
    float4 w3r[4];
    if (tid < 144) {
        const float* wg = W3 + (tid >> 4) * 128 + (tid & 7) * 16;
        #pragma unroll
        for (int kk = 0; kk < 4; kk++)
            w3r[kk] = *reinterpret_cast<const float4*>(wg + kk * 4);
    }

    for (int idx = tid; idx < RR * Dn; idx += NTH) {
        int r = idx >> 8, d = idx & 255;
        s.csr[r][d] = dense_cs[s.brow[r] * Dn + d];
    }
    __syncthreads();
    if (tid < RR) {
        float y = y0[s.brow[tid]];
        s.Yts[tid][0] = y; s.Ycur[tid][0] = y;
        out[s.brow[tid] * Tn] = y;       // t = 0 sample (dup rows: same value)
    }
    __syncthreads();

    // ---- time integration -------------------------------------------------
    for (int step = 0; step < Tn - 1; step++) {
        const float ta  = s.tsm[step];
        const float dtf = (s.tsm[step + 1] - ta) * 0.5f;
        // alive flags are constant over the whole step (exact: ta > tend
        // implies every stage time t >= ta > tend -> vf == 0, Y frozen)
        const bool alive0 = (ta <= s.tend[0]);
        const bool alive1 = (ta <= s.tend[1]);
        if (ta <= s.tendmax) {
            const bool aliveE = e ? alive1 : alive0;   // warp-uniform
            for (int sub = 0; sub < 2; sub++) {
                const float t0 = ta + sub * dtf;
                for (int st = 0; st < 4; st++) {
                    const float t = t0 + ((st == 0) ? 0.f : (st == 3) ? dtf : 0.5f * dtf);

                    // ---- layer 1: one (unit,row) each; skip dead row ----
                    if (aliveE) {
                        int ii = (int)ceilf(t);
                        ii = max(1, min(Dn - 1, ii));
                        float wc = t - (float)(ii - 1);
                        wc = fminf(fmaxf(wc, 0.f), 1.f);
                        float cl = s.csr[e][ii - 1];
                        float c  = fmaf(wc, s.csr[e][ii] - cl, cl);
                        float4 yA = *reinterpret_cast<const float4*>(&s.Yts[e][0]);
                        float4 yB = *reinterpret_cast<const float4*>(&s.Yts[e][4]);
                        float  y8 = s.Yts[e][8];
                        float a0 = base1;
                        float a1 = w1t * t;
                        a0 = fmaf(w1c,   c,    a0);
                        a1 = fmaf(w1a[0], yA.x, a1);
                        a0 = fmaf(w1a[1], yA.y, a0);
                        a1 = fmaf(w1a[2], yA.z, a1);
                        a0 = fmaf(w1a[3], yA.w, a0);
                        a1 = fmaf(w1a[4], yB.x, a1);
                        a0 = fmaf(w1a[5], yB.y, a0);
                        a1 = fmaf(w1a[6], yB.z, a1);
                        a0 = fmaf(w1a[7], yB.w, a0);
                        a1 = fmaf(w1a[8], y8,   a1);
                        s.h1[e][u1] = tanh_fast(a0 + a1);
                    }
                    __syncthreads();

                    // ---- layer 2 partials: skip dead rows (CTA-uniform) ----
                    {
                        #pragma unroll
                        for (int r = 0; r < RR; r++) {
                            if (r == 0 ? alive0 : alive1) {
                                u64 a0 = 0ull, a1 = 0ull, a2 = 0ull, a3 = 0ull;
                                const ulonglong2* hb =
                                    reinterpret_cast<const ulonglong2*>(&s.h1[r][h * 64]);
                                #pragma unroll
                                for (int m = 0; m < 8; m++) {
                                    ulonglong2 v0 = hb[2 * m];   // warp-uniform: broadcast
                                    a0 = fma2(W2r[4 * m],     v0.x, a0);
                                    a1 = fma2(W2r[4 * m + 1], v0.y, a1);
                                    ulonglong2 v1 = hb[2 * m + 1];
                                    a2 = fma2(W2r[4 * m + 2], v1.x, a2);
                                    a3 = fma2(W2r[4 * m + 3], v1.y, a3);
                                }
                                float2 f = unpk(add2(add2(a0, a1), add2(a2, a3)));
                                s.part[h][r][u2] = f.x + f.y;
                            }
                        }
                    }
                    __syncthreads();

                    // ---- layer 2 combine: skip dead row ----
                    if (aliveE)
                        s.h2[e][u1] = tanh_fast(s.part[0][e][u1] + s.part[1][e][u1] + b2r);
                    __syncthreads();

                    // ---- layer 3 + constraint + gating + RK bookkeeping ----
                    // UNGUARDED (static shfl masks): dead rows produce acc=0.
                    if (tid < 144) {
                        const unsigned mask = (tid < 128) ? 0xffffffffu : 0x0000ffffu;
                        const int q  = tid & 7;          // 16-k slice
                        const int r  = (tid >> 3) & 1;   // row
                        const int i3 = tid >> 4;         // output unit 0..8
                        const float4* hv = reinterpret_cast<const float4*>(&s.h2[r][q * 16]);
                        float ax = 0.f, ay = 0.f, az = 0.f, aw = 0.f;
                        #pragma unroll
                        for (int kk = 0; kk < 4; kk++) {
                            float4 a = w3r[kk], b = hv[kk];
                            ax = fmaf(a.x, b.x, ax);
                            ay = fmaf(a.y, b.y, ay);
                            az = fmaf(a.z, b.z, az);
                            aw = fmaf(a.w, b.w, aw);
                        }
                        float acc = (ax + ay) + (az + aw);
                        acc += __shfl_xor_sync(mask, acc, 1);
                        acc += __shfl_xor_sync(mask, acc, 2);
                        acc += __shfl_xor_sync(mask, acc, 4);
                        if (q == 0) {
                            acc += s.b3s[i3];
                            if (i3 == 0) acc = -__cosf(acc);
                            if (t > s.tend[r]) acc = 0.f;     // per-sample stop
                            float ks;
                            if (st == 0) { ks = acc; s.ksum[r][i3] = ks; }
                            else {
                                ks = s.ksum[r][i3];
                                if (st < 3) { ks += 2.f * acc; s.ksum[r][i3] = ks; }
                            }
                            if (st < 3) {
                                float cY = (st == 2) ? dtf : 0.5f * dtf;
                                s.Yts[r][i3] = s.Ycur[r][i3] + cY * acc;
                            } else {
                                float y = s.Ycur[r][i3]
                                        + (dtf * (1.0f / 6.0f)) * (ks + acc);
                                s.Ycur[r][i3] = y;
                                s.Yts[r][i3]  = y;
                            }
                        }
                    }
                    __syncthreads();
                }
            }
        }
        if (tid < RR)
            out[s.brow[tid] * Tn + step + 1] = s.Ycur[tid][0];
    }
}

extern "C" void kernel_launch(void* const* d_in, const int* in_sizes, int n_in,
                              void* d_out, int out_size)
{
    (void)in_sizes; (void)n_in; (void)out_size;
    sort_kernel<<<1, 128>>>((const int*)d_in[3]);
    node_kernel<<<NCTA, NTH>>>(
        (const float*)d_in[0],   // ts
        (const float*)d_in[1],   // y0
        (const float*)d_in[2],   // latent_vec
        (const int*)  d_in[3],   // length
        (const float*)d_in[4],   // dense_ts (arange -> index math)
        (const float*)d_in[5],   // dense_cs
        (const float*)d_in[6],   // W1
        (const float*)d_in[7],   // b1
        (const float*)d_in[8],   // W2
        (const float*)d_in[9],   // b2
        (const float*)d_in[10],  // W3
        (const float*)d_in[11],  // b3
        (float*)d_out);
}